// round 5
// baseline (speedup 1.0000x reference)
#include <cuda_runtime.h>
#include <math.h>
#include <stdint.h>

#define BATCH 16
#define H 1024
#define W 1024
#define HW (H * W)
#define CAP 262144
#define BUF 4096
#define NSAMP 4096
#define TWO_PI_F 6.28318530717958647692f
#define STEP_F 0.78539816339744830962f
#define EPSV 1e-6f

// global 0-based ranks: floor/ceil element of quantile positions 20971.5 and 1027603.5
__constant__ int c_ranks[4] = {20971, 20972, 1027603, 1027604};
// sample-rank walk targets: L0, H0, L1, H1  (pn0=82, pn1=4014, margin 96)
__constant__ int c_wrank[4] = {0, 178, 3918, 4095};

// ---------------- device scratch ----------------
__device__ unsigned g_cnt[BATCH][2];
__device__ unsigned g_below[BATCH][2];
__device__ unsigned g_cand[BATCH][2][CAP];
__device__ float    g_rlo[BATCH][2];
__device__ float    g_rhi[BATCH][2];
__device__ int      g_snt[BATCH][2];
__device__ int      g_grank[BATCH][2][4];   // global ranks of targets in each slot
__device__ int      g_stid[BATCH][2][4];
__device__ int      g_fail[BATCH];
__device__ float    g_qval[BATCH][4];

__constant__ int c_dy[8] = {0, -1, -1, -1, 0, 1, 1, 1};
__constant__ int c_dx[8] = {1, 1, 0, -1, -1, -1, 0, 1};

__device__ __forceinline__ unsigned f2key(float f) {
    unsigned u = __float_as_uint(f);
    return (u & 0x80000000u) ? ~u : (u | 0x80000000u);
}
__device__ __forceinline__ float key2f(unsigned k) {
    unsigned u = (k & 0x80000000u) ? (k & 0x7fffffffu) : ~k;
    return __uint_as_float(u);
}

// ---------------- warp-parallel histogram walk (full-mask shuffles only) ----------------
__device__ __forceinline__ int warp_walk(const unsigned* hist, int nb, int& rank) {
    int lane = threadIdx.x & 31;
    int chunk = nb / 32;
    const unsigned* hc = hist + lane * chunk;
    unsigned s = 0;
    for (int j = 0; j < chunk; j++) s += hc[j];
    unsigned inc = s;
#pragma unroll
    for (int o = 1; o < 32; o <<= 1) {
        unsigned v = __shfl_up_sync(0xffffffffu, inc, o);
        if (lane >= o) inc += v;
    }
    unsigned ex = inc - s;
    unsigned ball = __ballot_sync(0xffffffffu, (int)ex <= rank);
    int sel = 31 - __clz(ball);
    int d = 0, r = rank;
    if (lane == sel) {
        r = rank - (int)ex;
        d = lane * chunk;
        for (int j = 0; j < chunk; j++) {
            unsigned c = hc[j];
            if (r < (int)c) { d = lane * chunk + j; break; }
            r -= (int)c;
        }
    }
    d = __shfl_sync(0xffffffffu, d, sel);
    r = __shfl_sync(0xffffffffu, r, sel);
    rank = r;
    return d;
}

// ---------------- sampled bounds: one block per batch ----------------
__global__ __launch_bounds__(256) void k_bounds(const float* __restrict__ x) {
    __shared__ unsigned h[8192];
    __shared__ int sb[4];
    int b = blockIdx.x;
    const float* xb = x + (size_t)b * HW;
    for (int i = threadIdx.x; i < 8192; i += blockDim.x) h[i] = 0u;
    __syncthreads();
    // 4096 samples: 64 chunks of 64 contiguous floats, chunk c at offset c*16384
    for (int i = threadIdx.x; i < NSAMP; i += blockDim.x) {
        int idx = ((i >> 6) << 14) + (i & 63);
        atomicAdd(&h[f2key(xb[idx]) >> 19], 1u);
    }
    __syncthreads();
    int w = threadIdx.x >> 5;
    if (w < 4) {
        int r = c_wrank[w];
        int d = warp_walk(h, 8192, r);
        if ((threadIdx.x & 31) == 0) sb[w] = d;
    }
    __syncthreads();
    if (threadIdx.x == 0) {
        float inf = __int_as_float(0x7f800000);
        bool merged = (sb[2] <= sb[1]);
        int h0bin = merged ? sb[3] : sb[1];
        g_rlo[b][0] = key2f((unsigned)sb[0] << 19);
        g_rhi[b][0] = (h0bin == 8191) ? inf : key2f(((unsigned)h0bin + 1u) << 19);
        g_cnt[b][0] = 0u; g_cnt[b][1] = 0u;
        g_below[b][0] = 0u; g_below[b][1] = 0u;
        g_fail[b] = 0;
        if (merged) {
            g_snt[b][0] = 4; g_snt[b][1] = 0;
            g_rlo[b][1] = inf; g_rhi[b][1] = inf;
            for (int t = 0; t < 4; t++) { g_stid[b][0][t] = t; g_grank[b][0][t] = c_ranks[t]; }
        } else {
            g_snt[b][0] = 2; g_snt[b][1] = 2;
            g_rlo[b][1] = key2f((unsigned)sb[2] << 19);
            g_rhi[b][1] = (sb[3] == 8191) ? inf : key2f(((unsigned)sb[3] + 1u) << 19);
            for (int t = 0; t < 2; t++) {
                g_stid[b][0][t] = t;     g_grank[b][0][t] = c_ranks[t];
                g_stid[b][1][t] = 2 + t; g_grank[b][1][t] = c_ranks[2 + t];
            }
        }
    }
}

// ---------------- collect candidates + exact below-counts ----------------
__global__ __launch_bounds__(256) void k_collect(const float* __restrict__ x) {
    __shared__ unsigned scnt[2];
    __shared__ unsigned sbase[2];
    __shared__ unsigned sbuf[2][BUF];
    int b = blockIdx.y;
    if (threadIdx.x < 2) scnt[threadIdx.x] = 0u;
    __syncthreads();
    float l0 = g_rlo[b][0], h0 = g_rhi[b][0];
    float l1 = g_rlo[b][1], h1 = g_rhi[b][1];
    unsigned below0 = 0, below1 = 0;

    const float4* xb = (const float4*)(x + (size_t)b * HW);
    const int nvec = HW / 4;
    for (int i = blockIdx.x * blockDim.x + threadIdx.x; i < nvec; i += gridDim.x * blockDim.x) {
        float4 v4 = xb[i];
        float vs[4] = {v4.x, v4.y, v4.z, v4.w};
#pragma unroll
        for (int e = 0; e < 4; e++) {
            float v = vs[e];
            below0 += (v < l0);
            below1 += (v < l1);
            int s = -1;
            if (v >= l0 && v < h0) s = 0;
            else if (v >= l1 && v < h1) s = 1;
            if (s >= 0) {
                unsigned p = atomicAdd(&scnt[s], 1u);
                if (p < BUF) sbuf[s][p] = f2key(v);
                else {
                    unsigned gi = atomicAdd(&g_cnt[b][s], 1u);
                    if (gi < CAP) g_cand[b][s][gi] = f2key(v);
                }
            }
        }
    }
    // warp-reduce below counts, lane 0 flushes
#pragma unroll
    for (int o = 16; o > 0; o >>= 1) {
        below0 += __shfl_down_sync(0xffffffffu, below0, o);
        below1 += __shfl_down_sync(0xffffffffu, below1, o);
    }
    if ((threadIdx.x & 31) == 0) {
        atomicAdd(&g_below[b][0], below0);
        atomicAdd(&g_below[b][1], below1);
    }
    __syncthreads();
    if (threadIdx.x < 2) {
        unsigned m = min(scnt[threadIdx.x], (unsigned)BUF);
        sbase[threadIdx.x] = atomicAdd(&g_cnt[b][threadIdx.x], m);
    }
    __syncthreads();
#pragma unroll
    for (int s = 0; s < 2; s++) {
        unsigned m = min(scnt[s], (unsigned)BUF);
        unsigned base = sbase[s];
        for (unsigned j = threadIdx.x; j < m; j += blockDim.x)
            if (base + j < CAP) g_cand[b][s][base + j] = sbuf[s][j];
    }
}

// ---------------- exact 3-level select over candidate keys; verify ranks ----------------
__global__ void k_select() {
    int b = blockIdx.x >> 1, s = blockIdx.x & 1;
    __shared__ unsigned h1[2048];
    __shared__ unsigned hT[4][2048];
    __shared__ int s_d1[4], s_d2[4], s_rank[4], s_bad;
    int nt = g_snt[b][s];
    if (nt == 0) return;
    unsigned n = g_cnt[b][s];
    unsigned below = g_below[b][s];
    if (threadIdx.x == 0) {
        int bad = (n > CAP);
        for (int t = 0; t < nt; t++) {
            int r = g_grank[b][s][t] - (int)below;
            if (r < 0 || r >= (int)n) bad = 1;
            s_rank[t] = r;
        }
        s_bad = bad;
        if (bad) g_fail[b] = 1;
    }
    __syncthreads();
    if (s_bad) return;
    const unsigned* cand = g_cand[b][s];
    int w = threadIdx.x >> 5;

    for (int i = threadIdx.x; i < 2048; i += blockDim.x) h1[i] = 0u;
    __syncthreads();
    for (unsigned i = threadIdx.x; i < n; i += blockDim.x)
        atomicAdd(&h1[cand[i] >> 21], 1u);
    __syncthreads();
    if (w < nt) {
        int r = s_rank[w];
        int d = warp_walk(h1, 2048, r);
        if ((threadIdx.x & 31) == 0) { s_d1[w] = d; s_rank[w] = r; }
    }
    __syncthreads();
    for (int i = threadIdx.x; i < 4 * 2048; i += blockDim.x) ((unsigned*)hT)[i] = 0u;
    __syncthreads();
    for (unsigned i = threadIdx.x; i < n; i += blockDim.x) {
        unsigned k = cand[i];
        unsigned p = k >> 21;
        unsigned dig = (k >> 10) & 2047u;
        for (int tt = 0; tt < nt; tt++)
            if (p == (unsigned)s_d1[tt]) atomicAdd(&hT[tt][dig], 1u);
    }
    __syncthreads();
    if (w < nt) {
        int r = s_rank[w];
        int d = warp_walk(&hT[w][0], 2048, r);
        if ((threadIdx.x & 31) == 0) { s_d2[w] = d; s_rank[w] = r; }
    }
    __syncthreads();
    for (int i = threadIdx.x; i < 4 * 2048; i += blockDim.x) ((unsigned*)hT)[i] = 0u;
    __syncthreads();
    for (unsigned i = threadIdx.x; i < n; i += blockDim.x) {
        unsigned k = cand[i];
        unsigned p = k >> 10;
        for (int tt = 0; tt < nt; tt++)
            if (p == (((unsigned)s_d1[tt] << 11) | (unsigned)s_d2[tt]))
                atomicAdd(&hT[tt][k & 1023u], 1u);
    }
    __syncthreads();
    if (w < nt) {
        int r = s_rank[w];
        int d = warp_walk(&hT[w][0], 1024, r);
        if ((threadIdx.x & 31) == 0) {
            unsigned key = ((unsigned)s_d1[w] << 21) | ((unsigned)s_d2[w] << 10) | (unsigned)d;
            g_qval[b][g_stid[b][s][w]] = key2f(key);
        }
    }
}

// ---------------- rescue: full exact per-batch select (runs only on sampled-bounds miss) ----------------
__global__ void k_rescue(const float* __restrict__ x) {
    int b = blockIdx.x;
    if (!g_fail[b]) return;
    __shared__ unsigned h[8192];
    __shared__ int sbin[4], sd2[4], srnk[4];
    const float* xb = x + (size_t)b * HW;

    for (int i = threadIdx.x; i < 8192; i += blockDim.x) h[i] = 0u;
    __syncthreads();
    for (int i = threadIdx.x; i < HW; i += blockDim.x)
        atomicAdd(&h[f2key(xb[i]) >> 19], 1u);
    __syncthreads();
    int w = threadIdx.x >> 5;
    if (w < 4) {
        int r = c_ranks[w];
        int d = warp_walk(h, 8192, r);
        if ((threadIdx.x & 31) == 0) { sbin[w] = d; srnk[w] = r; }
    }
    __syncthreads();
    for (int t = 0; t < 4; t++) {
        for (int i = threadIdx.x; i < 2048; i += blockDim.x) h[i] = 0u;
        __syncthreads();
        unsigned tb = (unsigned)sbin[t];
        for (int i = threadIdx.x; i < HW; i += blockDim.x) {
            unsigned k = f2key(xb[i]);
            if ((k >> 19) == tb) atomicAdd(&h[(k >> 8) & 2047u], 1u);
        }
        __syncthreads();
        if (w == 0) {
            int r = srnk[t];
            int d = warp_walk(h, 2048, r);
            if ((threadIdx.x & 31) == 0) { sd2[t] = d; srnk[t] = r; }
        }
        __syncthreads();
    }
    for (int t = 0; t < 4; t++) {
        for (int i = threadIdx.x; i < 256; i += blockDim.x) h[i] = 0u;
        __syncthreads();
        unsigned pre = ((unsigned)sbin[t] << 11) | (unsigned)sd2[t];
        for (int i = threadIdx.x; i < HW; i += blockDim.x) {
            unsigned k = f2key(xb[i]);
            if ((k >> 8) == pre) atomicAdd(&h[k & 255u], 1u);
        }
        __syncthreads();
        if (w == 0) {
            int r = srnk[t];
            int d = warp_walk(h, 256, r);
            if ((threadIdx.x & 31) == 0)
                g_qval[b][t] = key2f(((unsigned)sbin[t] << 19) | ((unsigned)sd2[t] << 8) | (unsigned)d);
        }
        __syncthreads();
    }
}

// ---------------- fused: normalize + sobel + atan2 + dir-max + end map ----------------
#define TS 32
#define HALO 6
#define SW (TS + 2 * HALO)   // 44
#define SPITCH (SW + 1)      // 45

__global__ __launch_bounds__(256) void k_fused(const float* __restrict__ x,
                                               float* __restrict__ emap,
                                               float* __restrict__ binsf,
                                               float* __restrict__ xnout) {
    __shared__ float tile[SW * SPITCH];
    int b = blockIdx.z;
    int bx = blockIdx.x * TS, by = blockIdx.y * TS;
    const float* xb = x + (size_t)b * HW;

    float q0 = g_qval[b][0], q1 = g_qval[b][1];
    float q2 = g_qval[b][2], q3 = g_qval[b][3];
    float lo = q0 + 0.5f * (q1 - q0);
    float hi = q2 + 0.5f * (q3 - q2);
    float den = hi - lo + EPSV;

    int lane = threadIdx.x & 31;
    int wid = threadIdx.x >> 5;
    bool interior = (bx >= HALO) && (bx + TS + HALO <= W) && (by >= HALO) && (by + TS + HALO <= H);
    if (interior) {
        const float* src = xb + (size_t)(by - HALO) * W + (bx - HALO);
        for (int r = wid; r < SW; r += 8)
            for (int c = lane; c < SW; c += 32)
                tile[r * SPITCH + c] = fminf(fmaxf((src[r * W + c] - lo) / den, 0.f), 1.f);
    } else {
        for (int r = wid; r < SW; r += 8)
            for (int c = lane; c < SW; c += 32) {
                int gy = by + r - HALO, gx = bx + c - HALO;
                float v = 0.f;
                if ((unsigned)gy < H && (unsigned)gx < W)
                    v = fminf(fmaxf((xb[gy * W + gx] - lo) / den, 0.f), 1.f);
                tile[r * SPITCH + c] = v;
            }
    }
    __syncthreads();

#pragma unroll
    for (int k = 0; k < 4; k++) {
        int ly = wid + k * 8;
        int ty = ly + HALO, tx = lane + HALO;
        const float* t0 = &tile[ty * SPITCH + tx];

        float a00 = t0[-SPITCH - 1], a01 = t0[-SPITCH], a02 = t0[-SPITCH + 1];
        float a10 = t0[-1], a12 = t0[1];
        float a20 = t0[SPITCH - 1], a21 = t0[SPITCH], a22 = t0[SPITCH + 1];
        float gxs = (a02 - a00) + 2.f * (a12 - a10) + (a22 - a20);
        float gys = (a20 - a00) + 2.f * (a21 - a01) + (a22 - a02);

        float ang = atan2f(gys, gxs);
        if (ang < 0.f) ang += TWO_PI_F;
        int bin = (int)floorf(ang / STEP_F);
        bin = min(max(bin, 0), 7);
        int b8 = (bin + 2) & 7;

        int dy = c_dy[b8], dx = c_dx[b8];
        int step = dy * SPITCH + dx;
        float f = 0.f, w = 0.f;
#pragma unroll
        for (int r = 1; r <= 6; r++) {
            f = fmaxf(f, t0[-step * r]);
            w = fmaxf(w, t0[ step * r]);
        }
        float mn = fminf(f, w), mx = fmaxf(f, w);
        float ratio = mn / (mx + EPSV);
        float x0 = t0[0];
        float em = fminf(fmaxf(x0 * (1.f - ratio), 0.f), 1.f);

        size_t o = (size_t)b * HW + (size_t)(by + ly) * W + (bx + lane);
        emap[o] = em;
        if (binsf) binsf[o] = (float)b8;
        if (xnout) xnout[o] = x0;
    }
}

// ---------------- launch ----------------
extern "C" void kernel_launch(void* const* d_in, const int* in_sizes, int n_in,
                              void* d_out, int out_size) {
    const float* x = (const float*)d_in[0];
    float* out = (float*)d_out;
    const size_t N = (size_t)BATCH * HW;

    float* emap  = out;
    float* binsf = ((size_t)out_size >= 2 * N) ? out + N : nullptr;
    float* xnout = ((size_t)out_size >= 3 * N) ? out + 2 * N : nullptr;

    k_bounds<<<BATCH, 256>>>(x);
    k_collect<<<dim3(64, BATCH), 256>>>(x);
    k_select<<<BATCH * 2, 256>>>();
    k_rescue<<<BATCH, 256>>>(x);

    dim3 gf(W / TS, H / TS, BATCH);
    k_fused<<<gf, 256>>>(x, emap, binsf, xnout);
}

// round 6
// speedup vs baseline: 1.2132x; 1.2132x over previous
#include <cuda_runtime.h>
#include <math.h>
#include <stdint.h>

#define BATCH 16
#define H 1024
#define W 1024
#define HW (H * W)
#define CAP 262144
#define BUF 4096
#define NSAMP 4096
#define TWO_PI_F 6.28318530717958647692f
#define STEP_F 0.78539816339744830962f
#define EPSV 1e-6f

// global 0-based ranks: floor/ceil element of quantile positions 20971.5 and 1027603.5
__constant__ int c_ranks[4] = {20971, 20972, 1027603, 1027604};
// sample-rank walk targets: L0, H0, L1, H1  (pn0=82, pn1=4014, margin 96)
__constant__ int c_wrank[4] = {0, 178, 3918, 4095};

// ---------------- device scratch ----------------
__device__ unsigned g_cnt[BATCH][2];
__device__ unsigned g_below[BATCH][2];
__device__ unsigned g_cand[BATCH][2][CAP];
__device__ float    g_rlo[BATCH][2];
__device__ float    g_rhi[BATCH][2];
__device__ unsigned g_klo[BATCH][2];
__device__ unsigned g_khi[BATCH][2];
__device__ int      g_snt[BATCH][2];
__device__ int      g_grank[BATCH][2][4];
__device__ int      g_stid[BATCH][2][4];
__device__ int      g_fail[BATCH];
__device__ float    g_qval[BATCH][4];

__constant__ int c_dy[8] = {0, -1, -1, -1, 0, 1, 1, 1};
__constant__ int c_dx[8] = {1, 1, 0, -1, -1, -1, 0, 1};

__device__ __forceinline__ unsigned f2key(float f) {
    unsigned u = __float_as_uint(f);
    return (u & 0x80000000u) ? ~u : (u | 0x80000000u);
}
__device__ __forceinline__ float key2f(unsigned k) {
    unsigned u = (k & 0x80000000u) ? (k & 0x7fffffffu) : ~k;
    return __uint_as_float(u);
}

// ---------------- warp-parallel histogram walk (full-mask shuffles only) ----------------
__device__ __forceinline__ int warp_walk(const unsigned* hist, int nb, int& rank) {
    int lane = threadIdx.x & 31;
    int chunk = nb / 32;
    const unsigned* hc = hist + lane * chunk;
    unsigned s = 0;
    for (int j = 0; j < chunk; j++) s += hc[j];
    unsigned inc = s;
#pragma unroll
    for (int o = 1; o < 32; o <<= 1) {
        unsigned v = __shfl_up_sync(0xffffffffu, inc, o);
        if (lane >= o) inc += v;
    }
    unsigned ex = inc - s;
    unsigned ball = __ballot_sync(0xffffffffu, (int)ex <= rank);
    int sel = 31 - __clz(ball);
    int d = 0, r = rank;
    if (lane == sel) {
        r = rank - (int)ex;
        d = lane * chunk;
        for (int j = 0; j < chunk; j++) {
            unsigned c = hc[j];
            if (r < (int)c) { d = lane * chunk + j; break; }
            r -= (int)c;
        }
    }
    d = __shfl_sync(0xffffffffu, d, sel);
    r = __shfl_sync(0xffffffffu, r, sel);
    rank = r;
    return d;
}

// ---------------- sampled bounds: one block per batch ----------------
__global__ __launch_bounds__(256) void k_bounds(const float* __restrict__ x) {
    __shared__ unsigned h[8192];
    __shared__ int sb[4];
    int b = blockIdx.x;
    const float* xb = x + (size_t)b * HW;
    for (int i = threadIdx.x; i < 8192; i += blockDim.x) h[i] = 0u;
    __syncthreads();
    for (int i = threadIdx.x; i < NSAMP; i += blockDim.x) {
        int idx = ((i >> 6) << 14) + (i & 63);
        atomicAdd(&h[f2key(xb[idx]) >> 19], 1u);
    }
    __syncthreads();
    int w = threadIdx.x >> 5;
    if (w < 4) {
        int r = c_wrank[w];
        int d = warp_walk(h, 8192, r);
        if ((threadIdx.x & 31) == 0) sb[w] = d;
    }
    __syncthreads();
    if (threadIdx.x == 0) {
        float inf = __int_as_float(0x7f800000);
        bool merged = (sb[2] <= sb[1]);
        int h0bin = merged ? sb[3] : sb[1];
        unsigned klo0 = (unsigned)sb[0] << 19;
        unsigned khi0 = (h0bin == 8191) ? 0xFFFFFFFFu : (((unsigned)h0bin + 1u) << 19);
        g_klo[b][0] = klo0; g_khi[b][0] = khi0;
        g_rlo[b][0] = key2f(klo0);
        g_rhi[b][0] = (h0bin == 8191) ? inf : key2f(khi0);
        g_cnt[b][0] = 0u; g_cnt[b][1] = 0u;
        g_below[b][0] = 0u; g_below[b][1] = 0u;
        g_fail[b] = 0;
        if (merged) {
            g_snt[b][0] = 4; g_snt[b][1] = 0;
            g_rlo[b][1] = inf; g_rhi[b][1] = inf;
            g_klo[b][1] = 0xFFFFFFFFu; g_khi[b][1] = 0xFFFFFFFFu;
            for (int t = 0; t < 4; t++) { g_stid[b][0][t] = t; g_grank[b][0][t] = c_ranks[t]; }
        } else {
            g_snt[b][0] = 2; g_snt[b][1] = 2;
            unsigned klo1 = (unsigned)sb[2] << 19;
            unsigned khi1 = (sb[3] == 8191) ? 0xFFFFFFFFu : (((unsigned)sb[3] + 1u) << 19);
            g_klo[b][1] = klo1; g_khi[b][1] = khi1;
            g_rlo[b][1] = key2f(klo1);
            g_rhi[b][1] = (sb[3] == 8191) ? inf : key2f(khi1);
            for (int t = 0; t < 2; t++) {
                g_stid[b][0][t] = t;     g_grank[b][0][t] = c_ranks[t];
                g_stid[b][1][t] = 2 + t; g_grank[b][1][t] = c_ranks[2 + t];
            }
        }
    }
}

// ---------------- collect candidates + exact below-counts ----------------
__global__ __launch_bounds__(256) void k_collect(const float* __restrict__ x) {
    __shared__ unsigned scnt[2];
    __shared__ unsigned sbase[2];
    __shared__ unsigned sbuf[2][BUF];
    int b = blockIdx.y;
    if (threadIdx.x < 2) scnt[threadIdx.x] = 0u;
    __syncthreads();
    float l0 = g_rlo[b][0], h0 = g_rhi[b][0];
    float l1 = g_rlo[b][1], h1 = g_rhi[b][1];
    unsigned below0 = 0, below1 = 0;

    const float4* xb = (const float4*)(x + (size_t)b * HW);
    const int nvec = HW / 4;
    for (int i = blockIdx.x * blockDim.x + threadIdx.x; i < nvec; i += gridDim.x * blockDim.x) {
        float4 v4 = xb[i];
        float vs[4] = {v4.x, v4.y, v4.z, v4.w};
#pragma unroll
        for (int e = 0; e < 4; e++) {
            float v = vs[e];
            below0 += (v < l0);
            below1 += (v < l1);
            int s = -1;
            if (v >= l0 && v < h0) s = 0;
            else if (v >= l1 && v < h1) s = 1;
            if (s >= 0) {
                unsigned p = atomicAdd(&scnt[s], 1u);
                if (p < BUF) sbuf[s][p] = f2key(v);
                else {
                    unsigned gi = atomicAdd(&g_cnt[b][s], 1u);
                    if (gi < CAP) g_cand[b][s][gi] = f2key(v);
                }
            }
        }
    }
#pragma unroll
    for (int o = 16; o > 0; o >>= 1) {
        below0 += __shfl_down_sync(0xffffffffu, below0, o);
        below1 += __shfl_down_sync(0xffffffffu, below1, o);
    }
    if ((threadIdx.x & 31) == 0) {
        atomicAdd(&g_below[b][0], below0);
        atomicAdd(&g_below[b][1], below1);
    }
    __syncthreads();
    if (threadIdx.x < 2) {
        unsigned m = min(scnt[threadIdx.x], (unsigned)BUF);
        sbase[threadIdx.x] = atomicAdd(&g_cnt[b][threadIdx.x], m);
    }
    __syncthreads();
#pragma unroll
    for (int s = 0; s < 2; s++) {
        unsigned m = min(scnt[s], (unsigned)BUF);
        unsigned base = sbase[s];
        for (unsigned j = threadIdx.x; j < m; j += blockDim.x)
            if (base + j < CAP) g_cand[b][s][base + j] = sbuf[s][j];
    }
}

// ---------------- exact select over relative keys (dynamic shift schedule) ----------------
__global__ void k_select() {
    int b = blockIdx.x >> 1, s = blockIdx.x & 1;
    __shared__ unsigned hT[4][2048];
    __shared__ int s_rank[4];
    __shared__ unsigned s_pref[4];
    __shared__ int s_bad;
    int nt = g_snt[b][s];
    if (nt == 0) return;
    unsigned n = g_cnt[b][s];
    unsigned below = g_below[b][s];
    unsigned klo = g_klo[b][s];
    unsigned khi = g_khi[b][s];
    if (threadIdx.x == 0) {
        int bad = (n > CAP) || (n == 0);
        for (int t = 0; t < nt; t++) {
            int r = g_grank[b][s][t] - (int)below;
            if (r < 0 || r >= (int)n) bad = 1;
            s_rank[t] = r;
            s_pref[t] = 0u;
        }
        s_bad = bad;
        if (bad) g_fail[b] = 1;
    }
    __syncthreads();
    if (s_bad) return;
    const unsigned* cand = g_cand[b][s];
    int w = threadIdx.x >> 5;

    unsigned relmax = khi - klo - 1u;
    int bw = 32 - __clz(relmax | 1u);
    int sh0 = bw > 11 ? bw - 11 : 0;
    int sh1 = sh0 > 11 ? sh0 - 11 : 0;
    int shifts[3] = {sh0, sh1, 0};
    int prevsh = bw;

#pragma unroll
    for (int lvl = 0; lvl < 3; lvl++) {
        int cs = shifts[lvl];
        int bits = prevsh - cs;
        unsigned mask = (bits >= 32) ? 0xFFFFFFFFu : ((1u << bits) - 1u);
        for (int i = threadIdx.x; i < 4 * 2048; i += blockDim.x) ((unsigned*)hT)[i] = 0u;
        __syncthreads();
        if (lvl == 0) {
            for (unsigned i = threadIdx.x; i < n; i += blockDim.x) {
                unsigned rel = cand[i] - klo;
                atomicAdd(&hT[0][(rel >> cs) & mask], 1u);
            }
        } else {
            unsigned p0 = s_pref[0], p1 = s_pref[1], p2 = s_pref[2], p3 = s_pref[3];
            for (unsigned i = threadIdx.x; i < n; i += blockDim.x) {
                unsigned rel = cand[i] - klo;
                unsigned hib = rel >> prevsh;
                unsigned dig = (rel >> cs) & mask;
                if (hib == p0) atomicAdd(&hT[0][dig], 1u);
                if (nt > 1 && hib == p1) atomicAdd(&hT[1][dig], 1u);
                if (nt > 2 && hib == p2) atomicAdd(&hT[2][dig], 1u);
                if (nt > 3 && hib == p3) atomicAdd(&hT[3][dig], 1u);
            }
        }
        __syncthreads();
        if (w < nt) {
            int r = s_rank[w];
            const unsigned* hh = (lvl == 0) ? &hT[0][0] : &hT[w][0];
            int d = warp_walk(hh, 2048, r);
            if ((threadIdx.x & 31) == 0) {
                s_pref[w] = (s_pref[w] << bits) | (unsigned)d;
                s_rank[w] = r;
            }
        }
        __syncthreads();
        prevsh = cs;
        if (cs == 0) break;
    }
    if (w < nt && (threadIdx.x & 31) == 0) {
        unsigned key = klo + s_pref[w];
        g_qval[b][g_stid[b][s][w]] = key2f(key);
    }
}

// ---------------- rescue: full exact per-batch select (runs only on sampled-bounds miss) ----------------
__global__ void k_rescue(const float* __restrict__ x) {
    int b = blockIdx.x;
    if (!g_fail[b]) return;
    __shared__ unsigned h[8192];
    __shared__ int sbin[4], sd2[4], srnk[4];
    const float* xb = x + (size_t)b * HW;

    for (int i = threadIdx.x; i < 8192; i += blockDim.x) h[i] = 0u;
    __syncthreads();
    for (int i = threadIdx.x; i < HW; i += blockDim.x)
        atomicAdd(&h[f2key(xb[i]) >> 19], 1u);
    __syncthreads();
    int w = threadIdx.x >> 5;
    if (w < 4) {
        int r = c_ranks[w];
        int d = warp_walk(h, 8192, r);
        if ((threadIdx.x & 31) == 0) { sbin[w] = d; srnk[w] = r; }
    }
    __syncthreads();
    for (int t = 0; t < 4; t++) {
        for (int i = threadIdx.x; i < 2048; i += blockDim.x) h[i] = 0u;
        __syncthreads();
        unsigned tb = (unsigned)sbin[t];
        for (int i = threadIdx.x; i < HW; i += blockDim.x) {
            unsigned k = f2key(xb[i]);
            if ((k >> 19) == tb) atomicAdd(&h[(k >> 8) & 2047u], 1u);
        }
        __syncthreads();
        if (w == 0) {
            int r = srnk[t];
            int d = warp_walk(h, 2048, r);
            if ((threadIdx.x & 31) == 0) { sd2[t] = d; srnk[t] = r; }
        }
        __syncthreads();
    }
    for (int t = 0; t < 4; t++) {
        for (int i = threadIdx.x; i < 256; i += blockDim.x) h[i] = 0u;
        __syncthreads();
        unsigned pre = ((unsigned)sbin[t] << 11) | (unsigned)sd2[t];
        for (int i = threadIdx.x; i < HW; i += blockDim.x) {
            unsigned k = f2key(xb[i]);
            if ((k >> 8) == pre) atomicAdd(&h[k & 255u], 1u);
        }
        __syncthreads();
        if (w == 0) {
            int r = srnk[t];
            int d = warp_walk(h, 256, r);
            if ((threadIdx.x & 31) == 0)
                g_qval[b][t] = key2f(((unsigned)sbin[t] << 19) | ((unsigned)sd2[t] << 8) | (unsigned)d);
        }
        __syncthreads();
    }
}

// ---------------- fused: normalize + sobel + atan2 + dir-max + end map ----------------
#define TS 32
#define HALO 6
#define SW (TS + 2 * HALO)   // 44
#define SPITCH (SW + 1)      // 45

__global__ __launch_bounds__(256) void k_fused(const float* __restrict__ x,
                                               float* __restrict__ emap,
                                               float* __restrict__ binsf,
                                               float* __restrict__ xnout) {
    __shared__ float tile[SW * SPITCH];
    int b = blockIdx.z;
    int bx = blockIdx.x * TS, by = blockIdx.y * TS;
    const float* xb = x + (size_t)b * HW;

    float q0 = g_qval[b][0], q1 = g_qval[b][1];
    float q2 = g_qval[b][2], q3 = g_qval[b][3];
    float lo = q0 + 0.5f * (q1 - q0);
    float hi = q2 + 0.5f * (q3 - q2);
    float den = hi - lo + EPSV;

    int lane = threadIdx.x & 31;
    int wid = threadIdx.x >> 5;
    bool interior = (bx >= HALO) && (bx + TS + HALO <= W) && (by >= HALO) && (by + TS + HALO <= H);
    if (interior) {
        const float* src = xb + (size_t)(by - HALO) * W + (bx - HALO);
        for (int r = wid; r < SW; r += 8)
            for (int c = lane; c < SW; c += 32)
                tile[r * SPITCH + c] = fminf(fmaxf((src[r * W + c] - lo) / den, 0.f), 1.f);
    } else {
        for (int r = wid; r < SW; r += 8)
            for (int c = lane; c < SW; c += 32) {
                int gy = by + r - HALO, gx = bx + c - HALO;
                float v = 0.f;
                if ((unsigned)gy < H && (unsigned)gx < W)
                    v = fminf(fmaxf((xb[gy * W + gx] - lo) / den, 0.f), 1.f);
                tile[r * SPITCH + c] = v;
            }
    }
    __syncthreads();

#pragma unroll
    for (int k = 0; k < 4; k++) {
        int ly = wid + k * 8;
        int ty = ly + HALO, tx = lane + HALO;
        const float* t0 = &tile[ty * SPITCH + tx];

        float a00 = t0[-SPITCH - 1], a01 = t0[-SPITCH], a02 = t0[-SPITCH + 1];
        float a10 = t0[-1], a12 = t0[1];
        float a20 = t0[SPITCH - 1], a21 = t0[SPITCH], a22 = t0[SPITCH + 1];
        float gxs = (a02 - a00) + 2.f * (a12 - a10) + (a22 - a20);
        float gys = (a20 - a00) + 2.f * (a21 - a01) + (a22 - a02);

        float ang = atan2f(gys, gxs);
        if (ang < 0.f) ang += TWO_PI_F;
        int bin = (int)floorf(ang / STEP_F);
        bin = min(max(bin, 0), 7);
        int b8 = (bin + 2) & 7;

        int dy = c_dy[b8], dx = c_dx[b8];
        int step = dy * SPITCH + dx;
        float f = 0.f, w = 0.f;
#pragma unroll
        for (int r = 1; r <= 6; r++) {
            f = fmaxf(f, t0[-step * r]);
            w = fmaxf(w, t0[ step * r]);
        }
        float mn = fminf(f, w), mx = fmaxf(f, w);
        float ratio = mn / (mx + EPSV);
        float x0 = t0[0];
        float em = fminf(fmaxf(x0 * (1.f - ratio), 0.f), 1.f);

        size_t o = (size_t)b * HW + (size_t)(by + ly) * W + (bx + lane);
        emap[o] = em;
        if (binsf) binsf[o] = (float)b8;
        if (xnout) xnout[o] = x0;
    }
}

// ---------------- launch ----------------
extern "C" void kernel_launch(void* const* d_in, const int* in_sizes, int n_in,
                              void* d_out, int out_size) {
    const float* x = (const float*)d_in[0];
    float* out = (float*)d_out;
    const size_t N = (size_t)BATCH * HW;

    float* emap  = out;
    float* binsf = ((size_t)out_size >= 2 * N) ? out + N : nullptr;
    float* xnout = ((size_t)out_size >= 3 * N) ? out + 2 * N : nullptr;

    k_bounds<<<BATCH, 256>>>(x);
    k_collect<<<dim3(64, BATCH), 256>>>(x);
    k_select<<<BATCH * 2, 256>>>();
    k_rescue<<<BATCH, 256>>>(x);

    dim3 gf(W / TS, H / TS, BATCH);
    k_fused<<<gf, 256>>>(x, emap, binsf, xnout);
}